// round 1
// baseline (speedup 1.0000x reference)
#include <cuda_runtime.h>

// 5x5 median filter, reflect padding (numpy 'reflect' = mirror excluding edge),
// on [16, 3, 256, 256] fp32. Output same shape.
//
// Per pixel: sort 5 columns, sort 5 rank-rows (doubly-sorted matrix),
// then median = 7th of the 13 rank-feasible candidates via forgetful selection.

#define TX 32
#define TY 16
#define PAD 2
#define TILE_W (TX + 2 * PAD)  // 36
#define TILE_H (TY + 2 * PAD)  // 20
#define IMG_H 256
#define IMG_W 256

__device__ __forceinline__ void cas(float& a, float& b) {
    float lo = fminf(a, b);
    float hi = fmaxf(a, b);
    a = lo;
    b = hi;
}

// Insertion-sort network for 5 elements (10 CAS, provably correct).
__device__ __forceinline__ void sort5(float& a, float& b, float& c, float& d, float& e) {
    cas(a, b);
    cas(b, c); cas(a, b);
    cas(c, d); cas(b, c); cas(a, b);
    cas(d, e); cas(c, d); cas(b, c); cas(a, b);
}

__device__ __forceinline__ int reflect_idx(int i, int n) {
    i = (i < 0) ? -i : i;
    i = (i >= n) ? (2 * n - 2 - i) : i;
    return i;
}

__global__ __launch_bounds__(TX* TY, 2) void median5_kernel(
    const float* __restrict__ in, float* __restrict__ out) {
    __shared__ float tile[TILE_H][TILE_W];

    const int plane = blockIdx.z;  // b*c plane, 48 total
    const float* src = in + (size_t)plane * IMG_H * IMG_W;
    float* dst = out + (size_t)plane * IMG_H * IMG_W;

    const int bx = blockIdx.x * TX;
    const int by = blockIdx.y * TY;
    const int tid = threadIdx.y * TX + threadIdx.x;

    // Cooperative halo tile load with reflect padding.
    #pragma unroll
    for (int i = tid; i < TILE_H * TILE_W; i += TX * TY) {
        int r = i / TILE_W;
        int c = i - r * TILE_W;
        int gy = reflect_idx(by + r - PAD, IMG_H);
        int gx = reflect_idx(bx + c - PAD, IMG_W);
        tile[r][c] = src[gy * IMG_W + gx];
    }
    __syncthreads();

    // m[c][r]: column c of the 5x5 window, index r along rows.
    float m[5][5];
    #pragma unroll
    for (int c = 0; c < 5; c++) {
        #pragma unroll
        for (int r = 0; r < 5; r++)
            m[c][r] = tile[threadIdx.y + r][threadIdx.x + c];
        sort5(m[c][0], m[c][1], m[c][2], m[c][3], m[c][4]);
    }
    // Sort each rank-row across columns -> doubly sorted matrix.
    #pragma unroll
    for (int r = 0; r < 5; r++)
        sort5(m[0][r], m[1][r], m[2][r], m[3][r], m[4][r]);

    // 13 candidates (r,c) with (r+1)(c+1) <= 13 and (5-r)(5-c) <= 13:
    //   (0,3)(0,4) (1,2)(1,3)(1,4) (2,1)(2,2)(2,3) (3,0)(3,1)(3,2) (4,0)(4,1)
    // Global median == 7th smallest of these 13.  m[c][r] indexing.
    float w0 = m[3][0], w1 = m[4][0];
    float w2 = m[2][1], w3 = m[3][1], w4 = m[4][1];
    float w5 = m[1][2], w6 = m[2][2], w7 = m[3][2];
    const float s0 = m[0][3], s1 = m[1][3], s2 = m[2][3];
    const float s3 = m[0][4], s4 = m[1][4];

    // Forgetful selection: min->front, max->back, discard both, insert next.
    // minmax8: min -> w0, max -> w7
    cas(w0, w1); cas(w0, w2); cas(w0, w3); cas(w0, w4); cas(w0, w5); cas(w0, w6); cas(w0, w7);
    cas(w1, w7); cas(w2, w7); cas(w3, w7); cas(w4, w7); cas(w5, w7); cas(w6, w7);
    // working set now w1..w6; insert s0 in slot w0 -> minmax7 over w0..w6
    w0 = s0;
    cas(w0, w1); cas(w0, w2); cas(w0, w3); cas(w0, w4); cas(w0, w5); cas(w0, w6);
    cas(w1, w6); cas(w2, w6); cas(w3, w6); cas(w4, w6); cas(w5, w6);
    // working w1..w5; insert s1 -> minmax6 over w0..w5
    w0 = s1;
    cas(w0, w1); cas(w0, w2); cas(w0, w3); cas(w0, w4); cas(w0, w5);
    cas(w1, w5); cas(w2, w5); cas(w3, w5); cas(w4, w5);
    // working w1..w4; insert s2 -> minmax5 over w0..w4
    w0 = s2;
    cas(w0, w1); cas(w0, w2); cas(w0, w3); cas(w0, w4);
    cas(w1, w4); cas(w2, w4); cas(w3, w4);
    // working w1..w3; insert s3 -> minmax4 over w0..w3
    w0 = s3;
    cas(w0, w1); cas(w0, w2); cas(w0, w3);
    cas(w1, w3); cas(w2, w3);
    // working w1..w2; insert s4 -> minmax3 over w0..w2, median = middle
    w0 = s4;
    cas(w0, w1); cas(w0, w2);
    cas(w1, w2);

    dst[(by + threadIdx.y) * IMG_W + (bx + threadIdx.x)] = w1;
}

extern "C" void kernel_launch(void* const* d_in, const int* in_sizes, int n_in,
                              void* d_out, int out_size) {
    const float* image = (const float*)d_in[0];
    float* out = (float*)d_out;
    (void)in_sizes; (void)n_in; (void)out_size;

    dim3 block(TX, TY);
    dim3 grid(IMG_W / TX, IMG_H / TY, 16 * 3);
    median5_kernel<<<grid, block>>>(image, out);
}

// round 2
// speedup vs baseline: 1.4068x; 1.4068x over previous
#include <cuda_runtime.h>

// 5x5 median filter, reflect padding, [16,3,256,256] fp32.
//
// Per thread: 4 horizontally-adjacent output pixels.
//  - sort 8 shared columns (9-CAS optimal sort5 each)  -> 18 CAS/px amortized
//  - per pixel: rank-row SET selection (top2/top3/mid3/bot3/bot2) -> 34 CAS
//  - forgetful selection of rank-7-of-13 with tree minmax       -> 39 CAS
//  total ~91 CAS/px vs 148 in round 1.

#define BX 16
#define BY 16
#define PPT 4
#define OUT_W (BX * PPT)        // 64
#define OUT_H BY                // 16
#define PAD 2
#define TILE_W (OUT_W + 2*PAD)  // 68
#define TILE_H (OUT_H + 2*PAD)  // 20
#define IMG 256

__device__ __forceinline__ void cas(float& a, float& b) {
    float lo = fminf(a, b);
    float hi = fmaxf(a, b);
    a = lo;
    b = hi;
}

// Optimal 9-CAS sorting network for 5 elements.
// Comparators: (0,1)(3,4)(2,4)(2,3)(1,4)(0,3)(0,2)(1,3)(1,2)
__device__ __forceinline__ void sort5(float& a, float& b, float& c, float& d, float& e) {
    cas(a, b); cas(d, e); cas(c, e); cas(c, d); cas(b, e);
    cas(a, d); cas(a, c); cas(b, d); cas(b, c);
}

__device__ __forceinline__ int reflect_idx(int i, int n) {
    i = (i < 0) ? -i : i;
    i = (i >= n) ? (2 * n - 2 - i) : i;
    return i;
}

__global__ __launch_bounds__(BX * BY, 3) void median5_kernel(
    const float* __restrict__ in, float* __restrict__ out) {
    __shared__ float tile[TILE_H][TILE_W];

    const int plane = blockIdx.z;  // 48 planes
    const float* src = in + (size_t)plane * IMG * IMG;
    float* dst = out + (size_t)plane * IMG * IMG;

    const int bx = blockIdx.x * OUT_W;
    const int by = blockIdx.y * OUT_H;
    const int tid = threadIdx.y * BX + threadIdx.x;

    // Cooperative halo tile load with reflect padding.
    #pragma unroll
    for (int i = tid; i < TILE_H * TILE_W; i += BX * BY) {
        int r = i / TILE_W;
        int c = i - r * TILE_W;
        int gy = reflect_idx(by + r - PAD, IMG);
        int gx = reflect_idx(bx + c - PAD, IMG);
        tile[r][c] = src[gy * IMG + gx];
    }
    __syncthreads();

    // Load 8 columns x 5 rows via two float4 loads per row (16B-aligned:
    // tile row stride 68 floats = 272B = 17*16B; col offset 4*tx*4B).
    float col[8][5];
    #pragma unroll
    for (int r = 0; r < 5; r++) {
        const float4* rp =
            reinterpret_cast<const float4*>(&tile[threadIdx.y + r][threadIdx.x * PPT]);
        float4 lo = rp[0];
        float4 hi = rp[1];
        col[0][r] = lo.x; col[1][r] = lo.y; col[2][r] = lo.z; col[3][r] = lo.w;
        col[4][r] = hi.x; col[5][r] = hi.y; col[6][r] = hi.z; col[7][r] = hi.w;
    }
    #pragma unroll
    for (int j = 0; j < 8; j++)
        sort5(col[j][0], col[j][1], col[j][2], col[j][3], col[j][4]);

    float results[PPT];
    #pragma unroll
    for (int p = 0; p < PPT; p++) {
        float a, b, c, d, e;

        // Row 0 (column minima): need set of 2 largest.
        a = col[p][0]; b = col[p+1][0]; c = col[p+2][0]; d = col[p+3][0]; e = col[p+4][0];
        cas(a, b); cas(c, d); cas(b, d); cas(d, e);   // e = max5
        cas(a, b); cas(c, d); cas(b, d);              // d = 2nd max
        float w0 = e, w1 = d;

        // Row 1: need set of 3 largest (remove bottom-2).
        a = col[p][1]; b = col[p+1][1]; c = col[p+2][1]; d = col[p+3][1]; e = col[p+4][1];
        cas(a, b); cas(c, d); cas(a, c); cas(a, e);   // a = min5
        cas(b, c); cas(d, e); cas(b, d);              // b = 2nd min
        float w2 = c, w3 = d, w4 = e;

        // Row 2 (column medians): need middle-3 set (strip min and max).
        a = col[p][2]; b = col[p+1][2]; c = col[p+2][2]; d = col[p+3][2]; e = col[p+4][2];
        cas(a, b); cas(c, d); cas(a, c); cas(b, d); cas(a, e); cas(e, d);
        float w5 = b, w6 = c, w7 = e;                 // a = min5, d = max5

        // Row 3: need set of 3 smallest (remove top-2).
        a = col[p][3]; b = col[p+1][3]; c = col[p+2][3]; d = col[p+3][3]; e = col[p+4][3];
        cas(a, b); cas(c, d); cas(b, d); cas(d, e);   // e = max5
        cas(a, b); cas(c, d); cas(b, d);              // d = 2nd max
        float s0 = a, s1 = b, s2 = c;

        // Row 4 (column maxima): need set of 2 smallest.
        a = col[p][4]; b = col[p+1][4]; c = col[p+2][4]; d = col[p+3][4]; e = col[p+4][4];
        cas(a, b); cas(c, d); cas(a, c); cas(a, e);   // a = min5
        cas(b, c); cas(d, e); cas(b, d);              // b = 2nd min
        float s3 = a, s4 = b;

        // Forgetful selection: median = rank 7 (1-indexed) of the 13 candidates.
        // minmax8 (tree): w0 = min, w7 = max, survivors w1..w6.
        cas(w0, w1); cas(w2, w3); cas(w4, w5); cas(w6, w7);
        cas(w0, w2); cas(w4, w6); cas(w0, w4);
        cas(w1, w3); cas(w5, w7); cas(w3, w7);
        w0 = s0;
        // minmax7: w0 = min, w6 = max, survivors w1..w5.
        cas(w0, w1); cas(w2, w3); cas(w4, w5);
        cas(w0, w2); cas(w4, w6); cas(w0, w4);
        cas(w1, w3); cas(w5, w6); cas(w3, w6);
        w0 = s1;
        // minmax6: w0 = min, w5 = max, survivors w1..w4.
        cas(w0, w1); cas(w2, w3); cas(w4, w5);
        cas(w0, w2); cas(w0, w4);
        cas(w1, w3); cas(w3, w5);
        w0 = s2;
        // minmax5: w0 = min, w3 = max, survivors w1, w2, w4.
        cas(w0, w1); cas(w2, w3); cas(w0, w2); cas(w1, w3); cas(w0, w4); cas(w4, w3);
        w0 = s3;
        // minmax4 on (w0, w1, w2, w4): w0 = min, w4 = max, survivors w1, w2.
        cas(w0, w1); cas(w2, w4); cas(w0, w2); cas(w1, w4);
        w0 = s4;
        // median of 3 -> w1.
        cas(w0, w1); cas(w1, w2); cas(w0, w1);

        results[p] = w1;
    }

    const int gy = by + threadIdx.y;
    float4 r4 = make_float4(results[0], results[1], results[2], results[3]);
    *reinterpret_cast<float4*>(&dst[gy * IMG + bx + threadIdx.x * PPT]) = r4;
}

extern "C" void kernel_launch(void* const* d_in, const int* in_sizes, int n_in,
                              void* d_out, int out_size) {
    const float* image = (const float*)d_in[0];
    float* out = (float*)d_out;
    (void)in_sizes; (void)n_in; (void)out_size;

    dim3 block(BX, BY);
    dim3 grid(IMG / OUT_W, IMG / OUT_H, 16 * 3);
    median5_kernel<<<grid, block>>>(image, out);
}